// round 15
// baseline (speedup 1.0000x reference)
#include <cuda_runtime.h>

#define B_ 4
#define S_ 4096
#define NT (B_*S_)            // 16384 tokens
#define NBIN 128
#define NCHUNK (S_/32)        // 128 chunks per batch
#define WCUT 24.0f            // log2-domain pruning window
#define ALPHA 1.0201415515301256f   // log2(e)/sqrt(D=2)
#define PAD 64

// ---- scratch (__device__ globals: allocation-free) ----
__device__ float4 g_Q[NT*2];                 // p0,p1,-M, packed(lo|span<<8)
__device__ float4 g_SK [B_][(2*S_+PAD)/2];   // sorted keys, 2/float4, duplicated
__device__ float2 g_SSV[B_][(2*S_+PAD)/2];   // sorted s_v, 2/float2, duplicated
__device__ int    g_binStart[B_][2*NBIN+1];

// dynamic smem layout (bytes)
#define SM_CNT   0                     // ushort[128][128] = 32768
#define SM_SSK   32768                 // float2[4096]     = 32768
#define SM_SSV   65536                 // float [4096]     = 16384
#define SM_PG    81920                 // int[4][128]      = 2048
#define SM_BT    83968                 // int[128]         = 512
#define SM_BS    84480                 // int[129]         = 516
#define SMEM_SZ  85000

// Monotone angle surrogate ("diamond angle"): bin in [0, NBIN). No trig.
__device__ __forceinline__ int dbin(float xx, float yy)
{
    float ax = fabsf(xx), ay = fabsf(yy);
    float t = ay / (ax + ay + 1e-30f);                // [0,1]
    float a = (xx >= 0.f) ? ((yy >= 0.f) ? t : 4.f - t)
                          : ((yy >= 0.f) ? 2.f - t : 2.f + t);   // [0,4)
    int bn = (int)(a * 32.f);
    return min(max(bn, 0), NBIN-1);
}

// ---------------------------------------------------------------------------
// K1: per-batch monolith — prep + histogram + scan + smem scatter + stream.
// One block per batch, 1024 threads (warp = chunk, 4 chunks per warp).
// Records live in registers from compute through scatter; the sorted table is
// built in SMEM (scattered STS, cheap) and streamed to global coalesced.
// Deterministic: ranks from warp-match ballots, scans are fixed-order.
// ---------------------------------------------------------------------------
__global__ void __launch_bounds__(1024) sort_kernel(
    const float* __restrict__ x,   const float* __restrict__ freqs,
    const float* __restrict__ qkv, const float* __restrict__ vvec,
    const float* __restrict__ qu,  const float* __restrict__ ku)
{
    extern __shared__ char smem[];
    unsigned short (*cnt)[NBIN] = (unsigned short(*)[NBIN])(smem + SM_CNT);
    float2* ssk   = (float2*)(smem + SM_SSK);
    float*  ssv   = (float* )(smem + SM_SSV);
    int*    pg    = (int*)(smem + SM_PG);     // [4][NBIN]
    int*    binTot= (int*)(smem + SM_BT);
    int*    bs_s  = (int*)(smem + SM_BS);

    int b    = blockIdx.x;
    int tid  = threadIdx.x;
    int lane = tid & 31, warp = tid >> 5;      // 32 warps

    // zero histograms
    for (int t = tid; t < NCHUNK*NBIN/2; t += 1024)
        ((unsigned int*)(smem + SM_CNT))[t] = 0u;
    __syncthreads();

    // uniforms
    float ku0 = ku[0], ku1 = ku[1];
    float mk  = 0.5f * (ku0*ku0 + ku1*ku1);
    float qu00 = qu[0], qu01 = qu[1], qu10 = qu[2], qu11 = qu[3];
    float mq0 = 0.5f * (qu00*qu00 + qu01*qu01);
    float mq1 = 0.5f * (qu10*qu10 + qu11*qu11);

    // phase 1: per-token compute + histograms + in-chunk ranks (registers)
    float kr0[4], kr1[4], svr[4];
    int   binr[4], rankr[4];
#pragma unroll
    for (int t = 0; t < 4; t++) {
        int c = warp + 32*t;                   // chunk id
        int s = c*32 + lane;
        int i = b*S_ + s;
        const float* xp = x + i*5;
        float a = 0.f, av = 0.f;
#pragma unroll
        for (int j = 0; j < 5; j++) {
            float xv = xp[j];
            a  = fmaf(xv, qkv[j],  a);
            av = fmaf(xv, vvec[j], av);
        }
        float cc, sn;
        __sincosf(freqs[s], &sn, &cc);

        // key: rmsnorm(D=2) + rope
        float invk = rsqrtf(fmaf(a*a, mk, 1e-6f));
        float gk   = 16.f * a * invk;
        float kn0 = gk*ku0, kn1 = gk*ku1;
        float k0 = kn0*cc - kn1*sn;
        float k1 = kn0*sn + kn1*cc;
        int bin = dbin(k0, k1);
        kr0[t] = k0; kr1[t] = k1; svr[t] = av; binr[t] = bin;

        unsigned mask = __match_any_sync(0xffffffffu, bin);
        rankr[t] = __popc(mask & ((1u << lane) - 1u));
        if (rankr[t] == 0) cnt[c][bin] = (unsigned short)__popc(mask);

        // queries, both heads: p, -M, window bin range via vector rotation
#pragma unroll
        for (int h = 0; h < 2; h++) {
            float u0 = h ? qu10 : qu00, u1 = h ? qu11 : qu01;
            float mq = h ? mq1 : mq0;
            float inv = rsqrtf(fmaf(a*a, mq, 1e-6f));
            float gq  = 16.f * a * inv;
            float qn0 = gq*u0, qn1 = gq*u1;
            float p0 = ALPHA * (qn0*cc - qn1*sn);
            float p1 = ALPHA * (qn0*sn + qn1*cc);
            float M  = sqrtf(p0*p0 + p1*p1) * 22.627417f;  // |k| <= 16*sqrt(2)

            int lo, span;
            float cd = 1.f - WCUT / M;                     // cos(dmax); M=0 -> -inf
            if (!(cd > -0.9f)) { lo = 0; span = NBIN; }
            else {
                float sd = sqrtf(fmaxf(1.f - cd*cd, 0.f));
                float vlx = fmaf(p0, cd,  p1*sd), vly = fmaf(p1, cd, -p0*sd);
                float vhx = fmaf(p0, cd, -p1*sd), vhy = fmaf(p1, cd,  p0*sd);
                lo = dbin(vlx, vly);
                int hi = dbin(vhx, vhy);
                span = hi - lo; if (span < 0) span += NBIN;
            }
            g_Q[i*2 + h] = make_float4(p0, p1, -M,
                                       __uint_as_float((unsigned)lo | ((unsigned)span << 8)));
        }
    }
    __syncthreads();

    // phase 2: scans (group sums -> group scan -> bin scan -> offset rewrite)
    if (tid < 512) {
        int bin = tid & 127, g = tid >> 7;
        int s = 0;
#pragma unroll 8
        for (int c = g*32; c < g*32 + 32; c++) s += cnt[c][bin];
        pg[g*NBIN + bin] = s;
    }
    __syncthreads();
    if (tid < NBIN) {
        int e = 0;
#pragma unroll
        for (int g = 0; g < 4; g++) { int v = pg[g*NBIN + tid]; pg[g*NBIN + tid] = e; e += v; }
        binTot[tid] = e;
    }
    __syncthreads();
    if (tid < 32) {
        int v0 = binTot[4*lane], v1 = binTot[4*lane+1],
            v2 = binTot[4*lane+2], v3 = binTot[4*lane+3];
        int sum = v0 + v1 + v2 + v3;
        int run = sum;
#pragma unroll
        for (int o = 1; o < 32; o <<= 1) {
            int n = __shfl_up_sync(0xffffffffu, run, o);
            if (lane >= o) run += n;
        }
        int excl = run - sum;
        bs_s[4*lane]   = excl;
        bs_s[4*lane+1] = excl + v0;
        bs_s[4*lane+2] = excl + v0 + v1;
        bs_s[4*lane+3] = excl + v0 + v1 + v2;
        if (lane == 31) bs_s[NBIN] = run;
    }
    __syncthreads();
    if (tid < 512) {
        int bin = tid & 127, g = tid >> 7;
        int base = bs_s[bin] + pg[g*NBIN + bin];
#pragma unroll 8
        for (int c = g*32; c < g*32 + 32; c++) {
            int v = cnt[c][bin];
            cnt[c][bin] = (unsigned short)base;            // now: global offset
            base += v;
        }
    }
    if (tid <= 2*NBIN)
        g_binStart[b][tid] = (tid <= NBIN) ? bs_s[tid] : bs_s[tid-NBIN] + S_;
    __syncthreads();

    // phase 3: scatter into SMEM table (cheap STS; conflicts ~random)
#pragma unroll
    for (int t = 0; t < 4; t++) {
        int c = warp + 32*t;
        int pos = (int)cnt[c][binr[t]] + rankr[t];
        ssk[pos] = make_float2(kr0[t], kr1[t]);
        ssv[pos] = svr[t];
    }
    __syncthreads();

    // phase 4: stream sorted table to global, both duplicated copies, coalesced
    float2* skg = (float2*)g_SK[b];
    float*  svg = (float*)g_SSV[b];
    for (int idx = tid; idx < S_; idx += 1024) {
        float2 kv = ssk[idx];
        float  sv = ssv[idx];
        skg[idx]      = kv;
        skg[idx + S_] = kv;
        svg[idx]      = sv;
        svg[idx + S_] = sv;
    }
}

// ---------------------------------------------------------------------------
// K2: attention, 2 keys/lane, predicate-free, unroll 4 for MLP.
// Correctness: keys in [s1, s0a+64*trips) lie past the window edge =>
// score-M < -WCUT => e < 2^-24 (legit negligible terms). s1 <= s0a+S_ and
// 64 | S_ => reads never exceed one circle nor leave the duplicated table.
// ---------------------------------------------------------------------------
__global__ void __launch_bounds__(256) attn_kernel(
    const float* __restrict__ ov, const float* __restrict__ uv,
    const float* __restrict__ ou, float* __restrict__ out)
{
    __shared__ float s_r[8];
    int wid  = threadIdx.x >> 5;
    int lane = threadIdx.x & 31;
    int w = blockIdx.x * 8 + wid;                      // (q,h) id
    int q = w >> 1;
    int b = q >> 12;

    float4 Q = g_Q[w];
    float p0 = Q.x, p1 = Q.y, nM = Q.z;
    unsigned pk = __float_as_uint(Q.w);
    int lo = (int)(pk & 255u), span = (int)(pk >> 8);

    const int* bs = g_binStart[b];
    int s0  = bs[lo];
    int s0a = s0 & ~63;
    int s1  = (span >= NBIN) ? (s0a + S_) : min(bs[lo + span + 1], s0a + S_);
    int trips = (s1 - s0a + 63) >> 6;

    const float4* __restrict__ sk4 = g_SK[b];
    const float2* __restrict__ sv2 = g_SSV[b];

    float den = 0.f, num = 0.f;
    int p = (s0a >> 1) + lane;                         // pair index
#pragma unroll 4
    for (int t = 0; t < trips; t++, p += 32) {
        float4 kv = sk4[p];
        float2 sv = sv2[p];
        float scA = fmaf(p0, kv.x, fmaf(p1, kv.y, nM));  // <= 0
        float scB = fmaf(p0, kv.z, fmaf(p1, kv.w, nM));
        float eA, eB;
        asm("ex2.approx.ftz.f32 %0, %1;" : "=f"(eA) : "f"(scA));
        asm("ex2.approx.ftz.f32 %0, %1;" : "=f"(eB) : "f"(scB));
        den += eA;
        num = fmaf(eA, sv.x, num);
        den += eB;
        num = fmaf(eB, sv.y, num);
    }
#pragma unroll
    for (int o = 16; o; o >>= 1) {
        den += __shfl_xor_sync(0xffffffffu, den, o);
        num += __shfl_xor_sync(0xffffffffu, num, o);
    }
    if (lane == 0) s_r[wid] = num / den;
    __syncthreads();

    // even-head warps write the query's 5 outputs
    if (!(w & 1) && lane < 5) {
        float C0 = uv[0]*ov[0] + uv[1]*ov[1];
        float C1 = uv[0]*ov[2] + uv[1]*ov[3];
        float so = s_r[wid]*C0 + s_r[wid+1]*C1;
        out[q*5 + lane] = so * ou[lane];
    }
}

extern "C" void kernel_launch(void* const* d_in, const int* in_sizes, int n_in,
                              void* d_out, int out_size)
{
    const float* x     = (const float*)d_in[0];
    const float* freqs = (const float*)d_in[1];
    const float* qkv   = (const float*)d_in[2];
    const float* vv    = (const float*)d_in[3];
    const float* ov    = (const float*)d_in[4];
    const float* uv    = (const float*)d_in[5];
    const float* qu    = (const float*)d_in[6];
    const float* ku    = (const float*)d_in[7];
    const float* ou    = (const float*)d_in[8];

    cudaFuncSetAttribute(sort_kernel,
                         cudaFuncAttributeMaxDynamicSharedMemorySize, SMEM_SZ);
    sort_kernel<<<B_, 1024, SMEM_SZ>>>(x, freqs, qkv, vv, qu, ku);
    attn_kernel<<<NT*2/8, 256>>>(ov, uv, ou, (float*)d_out);
}